// round 1
// baseline (speedup 1.0000x reference)
#include <cuda_runtime.h>
#include <cstdint>

// Problem constants (fixed by the dataset)
#define B_   4
#define C_   256
#define H_   128
#define W_   128
#define Q_   100
#define OUT_ 7
#define BINS (OUT_ * OUT_)   // 49

// Scratch: channel-last SAT  S[b][y][x][c], inclusive 2-D prefix sum.
// 4*128*128*256 floats = 64 MB. __device__ global (no runtime alloc).
__device__ float g_sat[(size_t)B_ * H_ * W_ * C_];

// ---------------------------------------------------------------------------
// K1: transpose + x-cumsum.
// Block handles one (b, y, cgroup of 64 channels).
// Reads x[b][c][y][:] rows (coalesced), cumsums along x in smem,
// writes channel-last T[b][y][x][c] (coalesced across c).
// ---------------------------------------------------------------------------
__global__ __launch_bounds__(256) void k1_xscan(const float* __restrict__ x,
                                                float* __restrict__ T) {
    const int by = blockIdx.x;           // 0 .. B*H-1
    const int b  = by >> 7;
    const int y  = by & (H_ - 1);
    const int cg = blockIdx.y;           // 0..3, 64 channels each

    __shared__ float s[64][W_ + 1];      // pad to 129 -> conflict-free columns

    const int tid = threadIdx.x;
    const float* src = x + ((size_t)(b * C_ + cg * 64) * H_ + y) * W_;

    // load 64 rows of 128 (each row contiguous in gmem)
    #pragma unroll 4
    for (int i = tid; i < 64 * W_; i += 256) {
        int cl = i >> 7;                 // channel-local
        int xx = i & (W_ - 1);
        s[cl][xx] = src[(size_t)cl * (H_ * W_) + xx];
    }
    __syncthreads();

    // serial inclusive scan along x (64 threads, one per channel row)
    if (tid < 64) {
        float acc = s[tid][0];
        #pragma unroll 8
        for (int xx = 1; xx < W_; xx++) {
            acc += s[tid][xx];
            s[tid][xx] = acc;
        }
    }
    __syncthreads();

    // write channel-last: T[((b*H + y)*W + x)*C + cg*64 + cl]
    float* dst = T + ((size_t)(b * H_ + y) * W_) * C_ + cg * 64;
    #pragma unroll 4
    for (int i = tid; i < 64 * W_; i += 256) {
        int xx = i >> 6;
        int cl = i & 63;
        dst[(size_t)xx * C_ + cl] = s[cl][xx];
    }
}

// ---------------------------------------------------------------------------
// K2: y-cumsum in channel-last layout (in place).
// Thread per (b, x, c); consecutive threads -> consecutive c: coalesced.
// ---------------------------------------------------------------------------
__global__ __launch_bounds__(256) void k2_yscan(float* __restrict__ T) {
    const int g   = blockIdx.x * 256 + threadIdx.x;   // 0 .. B*W*C-1
    const int b   = g >> 15;                          // /(W*C)=32768
    const int rem = g & 32767;                        // x*C + c
    size_t base = (size_t)b * (H_ * W_ * C_) + rem;
    const size_t stride = (size_t)W_ * C_;

    float acc = 0.f;
    #pragma unroll 8
    for (int y = 0; y < H_; y++) {
        acc += T[base];
        T[base] = acc;
        base += stride;
    }
}

// ---------------------------------------------------------------------------
// K3: gather. One block per (b, q). 256 threads.
// Edges/areas precomputed in smem. Corner loads coalesced across c (channel-
// last SAT). Results staged in smem and written as one contiguous slab.
// ---------------------------------------------------------------------------
__global__ __launch_bounds__(256) void k3_gather(const int* __restrict__ rois,
                                                 const float* __restrict__ S,
                                                 float* __restrict__ out) {
    const int bq = blockIdx.x;           // 0 .. B*Q-1
    const int b  = bq / Q_;
    const int tid = threadIdx.x;

    __shared__ int   e_ys[OUT_], e_ye[OUT_], e_xs[OUT_], e_xe[OUT_];
    __shared__ float ia[BINS];
    __shared__ float stage[64][BINS + 2];   // pad 51 -> conflict-free

    const int* r = rois + bq * 5;        // [bidx, x1, y1, x2, y2]

    if (tid < OUT_) {
        int y1 = r[2], leny = r[4] - r[2];
        e_ys[tid] = y1 + (tid * leny) / OUT_;
        e_ye[tid] = y1 + ((tid + 1) * leny + (OUT_ - 1)) / OUT_;
    } else if (tid < 2 * OUT_) {
        int k = tid - OUT_;
        int x1 = r[1], lenx = r[3] - r[1];
        e_xs[k] = x1 + (k * lenx) / OUT_;
        e_xe[k] = x1 + ((k + 1) * lenx + (OUT_ - 1)) / OUT_;
    }
    __syncthreads();
    if (tid < BINS) {
        int oy = tid / OUT_, ox = tid % OUT_;
        ia[tid] = 1.0f / (float)((e_ye[oy] - e_ys[oy]) * (e_xe[ox] - e_xs[ox]));
    }
    __syncthreads();

    const int cl  = tid & 63;            // channel within 64-chunk
    const int sub = tid >> 6;            // 0..3: bin stripe
    const float* Sb = S + (size_t)b * (H_ * W_ * C_);

    for (int cg = 0; cg < 4; cg++) {
        const int c = cg * 64 + cl;

        for (int bin = sub; bin < BINS; bin += 4) {
            const int oy = bin / OUT_, ox = bin % OUT_;
            const int Ys = e_ys[oy], Ye = e_ye[oy];
            const int Xs = e_xs[ox], Xe = e_xe[ox];

            // padded-SAT fetch: pad index 0 -> 0, else SAT[y-1][x-1][c]
            float see = Sb[(((size_t)(Ye - 1) * W_) + (Xe - 1)) * C_ + c];
            float sse = (Ys == 0) ? 0.f
                      : Sb[(((size_t)(Ys - 1) * W_) + (Xe - 1)) * C_ + c];
            float ses = (Xs == 0) ? 0.f
                      : Sb[(((size_t)(Ye - 1) * W_) + (Xs - 1)) * C_ + c];
            float sss = (Ys == 0 || Xs == 0) ? 0.f
                      : Sb[(((size_t)(Ys - 1) * W_) + (Xs - 1)) * C_ + c];

            stage[cl][bin] = (see - sse - ses + sss) * ia[bin];
        }
        __syncthreads();

        // contiguous slab: out[((bq*C + cg*64 + cl)*49 + bin)]
        float* ob = out + ((size_t)bq * C_ + cg * 64) * BINS;
        #pragma unroll 4
        for (int i = tid; i < 64 * BINS; i += 256) {
            ob[i] = stage[i / BINS][i % BINS];
        }
        __syncthreads();
    }
}

// ---------------------------------------------------------------------------
extern "C" void kernel_launch(void* const* d_in, const int* in_sizes, int n_in,
                              void* d_out, int out_size) {
    const float* x    = (const float*)d_in[0];
    const int*   rois = (const int*)d_in[1];
    float*       out  = (float*)d_out;

    float* sat;
    cudaGetSymbolAddress((void**)&sat, g_sat);

    dim3 g1(B_ * H_, 4);
    k1_xscan<<<g1, 256>>>(x, sat);

    k2_yscan<<<(B_ * W_ * C_) / 256, 256>>>(sat);

    k3_gather<<<B_ * Q_, 256>>>(rois, sat, out);
}

// round 2
// speedup vs baseline: 1.1746x; 1.1746x over previous
#include <cuda_runtime.h>
#include <cstdint>

#define B_   4
#define C_   256
#define H_   128
#define W_   128
#define Q_   100
#define OUT_ 7
#define BINS (OUT_ * OUT_)   // 49

// Channel-last SAT scratch: S[b][y][x][c], 64 MB.
__device__ float g_sat[(size_t)B_ * H_ * W_ * C_];

// ---------------------------------------------------------------------------
// K1: transpose + x-cumsum (warp-shuffle scan, no serial smem chain).
// Block = (b, y, cgroup of 64 channels). Each warp scans 8 channel rows:
// coalesced float4 load -> register scan (3 adds + 5 shuffles) -> smem stage
// -> coalesced transposed write to channel-last layout.
// ---------------------------------------------------------------------------
__global__ __launch_bounds__(256) void k1_xscan(const float* __restrict__ x,
                                                float* __restrict__ T) {
    const int by = blockIdx.x;           // 0 .. B*H-1
    const int b  = by >> 7;
    const int y  = by & (H_ - 1);
    const int cg = blockIdx.y;           // 0..3

    __shared__ float s[64][W_ + 1];      // pad 129 -> conflict-free both phases

    const int tid  = threadIdx.x;
    const int lane = tid & 31;
    const int warp = tid >> 5;           // 8 warps, 8 rows each

    const float* src = x + ((size_t)(b * C_ + cg * 64) * H_ + y) * W_;

    #pragma unroll
    for (int r = 0; r < 8; r++) {
        const int cl = warp * 8 + r;
        float4 v = reinterpret_cast<const float4*>(
                       src + (size_t)cl * (H_ * W_))[lane];

        // local inclusive scan of 4
        v.y += v.x; v.z += v.y; v.w += v.z;

        // warp inclusive scan of lane sums
        float sum = v.w;
        #pragma unroll
        for (int off = 1; off < 32; off <<= 1) {
            float t = __shfl_up_sync(0xffffffffu, sum, off);
            if (lane >= off) sum += t;
        }
        const float pre = sum - v.w;     // exclusive prefix for this lane

        s[cl][4 * lane + 0] = v.x + pre;
        s[cl][4 * lane + 1] = v.y + pre;
        s[cl][4 * lane + 2] = v.z + pre;
        s[cl][4 * lane + 3] = v.w + pre;
    }
    __syncthreads();

    // transposed write: T[((b*H+y)*W + x)*C + cg*64 + cl]
    // consecutive tid -> consecutive cl (conflict-free smem, coalesced gmem)
    float* dst = T + ((size_t)(b * H_ + y) * W_) * C_ + cg * 64;
    #pragma unroll 8
    for (int i = tid; i < 64 * W_; i += 256) {
        const int xx = i >> 6;
        const int cl = i & 63;
        dst[(size_t)xx * C_ + cl] = s[cl][xx];
    }
}

// ---------------------------------------------------------------------------
// K2: y-cumsum in channel-last layout (in place), float4 per thread,
// unroll 8 for ~128B in flight per thread.
// ---------------------------------------------------------------------------
__global__ __launch_bounds__(256) void k2_yscan(float4* __restrict__ T4) {
    const int g   = blockIdx.x * 256 + threadIdx.x;   // 0 .. B*W*C/4 - 1
    const int b   = g >> 13;                          // / (W*C/4) = 8192
    const int rem = g & 8191;
    size_t base = (size_t)b * (H_ * W_ * C_ / 4) + rem;
    const size_t stride = (size_t)W_ * C_ / 4;        // 8192

    float4 acc = make_float4(0.f, 0.f, 0.f, 0.f);
    #pragma unroll 8
    for (int y = 0; y < H_; y++) {
        float4 v = T4[base];
        acc.x += v.x; acc.y += v.y; acc.z += v.z; acc.w += v.w;
        T4[base] = acc;
        base += stride;
    }
}

// ---------------------------------------------------------------------------
// K3: gather. Grid = (B*Q, 4 cgroups). 256 threads = 64 channels x 4 stripes.
// Corner loads coalesced across c; staged and written as contiguous slab.
// ---------------------------------------------------------------------------
__global__ __launch_bounds__(256) void k3_gather(const int* __restrict__ rois,
                                                 const float* __restrict__ S,
                                                 float* __restrict__ out) {
    const int bq = blockIdx.x;           // 0 .. B*Q-1
    const int cg = blockIdx.y;           // 0..3
    const int b  = bq / Q_;
    const int tid = threadIdx.x;

    __shared__ int   e_ys[OUT_], e_ye[OUT_], e_xs[OUT_], e_xe[OUT_];
    __shared__ float ia[BINS];
    __shared__ float stage[64][BINS + 2];   // pad 51 -> conflict-free

    const int* r = rois + bq * 5;        // [bidx, x1, y1, x2, y2]

    if (tid < OUT_) {
        int y1 = r[2], leny = r[4] - r[2];
        e_ys[tid] = y1 + (tid * leny) / OUT_;
        e_ye[tid] = y1 + ((tid + 1) * leny + (OUT_ - 1)) / OUT_;
    } else if (tid < 2 * OUT_) {
        int k = tid - OUT_;
        int x1 = r[1], lenx = r[3] - r[1];
        e_xs[k] = x1 + (k * lenx) / OUT_;
        e_xe[k] = x1 + ((k + 1) * lenx + (OUT_ - 1)) / OUT_;
    }
    __syncthreads();
    if (tid < BINS) {
        int oy = tid / OUT_, ox = tid % OUT_;
        ia[tid] = 1.0f / (float)((e_ye[oy] - e_ys[oy]) * (e_xe[ox] - e_xs[ox]));
    }
    __syncthreads();

    const int cl  = tid & 63;
    const int sub = tid >> 6;            // 0..3
    const int c   = cg * 64 + cl;
    const float* Sb = S + (size_t)b * (H_ * W_ * C_);

    #pragma unroll
    for (int bin = sub; bin < BINS; bin += 4) {
        const int oy = bin / OUT_, ox = bin % OUT_;
        const int Ys = e_ys[oy], Ye = e_ye[oy];
        const int Xs = e_xs[ox], Xe = e_xe[ox];

        float see = Sb[(((size_t)(Ye - 1) * W_) + (Xe - 1)) * C_ + c];
        float sse = (Ys == 0) ? 0.f
                  : Sb[(((size_t)(Ys - 1) * W_) + (Xe - 1)) * C_ + c];
        float ses = (Xs == 0) ? 0.f
                  : Sb[(((size_t)(Ye - 1) * W_) + (Xs - 1)) * C_ + c];
        float sss = (Ys == 0 || Xs == 0) ? 0.f
                  : Sb[(((size_t)(Ys - 1) * W_) + (Xs - 1)) * C_ + c];

        stage[cl][bin] = (see - sse - ses + sss) * ia[bin];
    }
    __syncthreads();

    // contiguous slab: out[(bq*C + cg*64 + cl)*49 + bin]
    float* ob = out + ((size_t)bq * C_ + cg * 64) * BINS;
    #pragma unroll 4
    for (int i = tid; i < 64 * BINS; i += 256) {
        ob[i] = stage[i / BINS][i % BINS];
    }
}

// ---------------------------------------------------------------------------
extern "C" void kernel_launch(void* const* d_in, const int* in_sizes, int n_in,
                              void* d_out, int out_size) {
    const float* x    = (const float*)d_in[0];
    const int*   rois = (const int*)d_in[1];
    float*       out  = (float*)d_out;

    float* sat;
    cudaGetSymbolAddress((void**)&sat, g_sat);

    dim3 g1(B_ * H_, 4);
    k1_xscan<<<g1, 256>>>(x, sat);

    k2_yscan<<<(B_ * W_ * C_ / 4) / 256, 256>>>((float4*)sat);

    dim3 g3(B_ * Q_, 4);
    k3_gather<<<g3, 256>>>(rois, sat, out);
}

// round 3
// speedup vs baseline: 1.3917x; 1.1848x over previous
#include <cuda_runtime.h>
#include <cstdint>

#define B_   4
#define C_   256
#define H_   128
#define W_   128
#define Q_   100
#define OUT_ 7
#define BINS (OUT_ * OUT_)   // 49

#define YT_  16              // rows per y-tile
#define NT_  (H_ / YT_)      // 8 y-tiles
#define CG_  16              // channels per K1 block
#define NCG_ (C_ / CG_)      // 16 channel groups

// Tile-local SAT (y-scan only within 16-row tiles), channel-last: S[b][y][x][c]
__device__ float g_sat[(size_t)B_ * H_ * W_ * C_];            // 64 MB
// Per-tile column sums and their exclusive y-tile prefix (offsets)
__device__ float g_cs [(size_t)B_ * NT_ * W_ * C_];           // 4 MB
__device__ float g_off[(size_t)B_ * NT_ * W_ * C_];           // 4 MB

// ---------------------------------------------------------------------------
// K1: fused x-scan + tile-local y-scan + transpose.
// Block = (b, ytile, cgroup of 16 ch). 8 warps, 2 channels per warp.
// Per y: coalesced float4 row load -> shuffle x-scan -> add to register
// y-accumulator -> smem stage -> coalesced channel-last write.
// After 16 rows, write the accumulator (tile column sum) to g_cs.
// ---------------------------------------------------------------------------
__global__ __launch_bounds__(256) void k1_fused(const float* __restrict__ x,
                                                float* __restrict__ S,
                                                float* __restrict__ cs) {
    const int gb = blockIdx.x;                 // 0 .. B*NT*NCG-1 = 511
    const int cg = gb & (NCG_ - 1);
    const int yt = (gb >> 4) & (NT_ - 1);
    const int b  = gb >> 7;

    const int tid  = threadIdx.x;
    const int lane = tid & 31;
    const int warp = tid >> 5;                 // 8 warps

    __shared__ float s[CG_][W_ + 1];           // ~8.25 KB

    float4 acc0 = make_float4(0.f, 0.f, 0.f, 0.f);
    float4 acc1 = make_float4(0.f, 0.f, 0.f, 0.f);

    const float* src = x + ((size_t)(b * C_ + cg * CG_) * H_ + yt * YT_) * W_;
    float* dstBase = S + ((size_t)(b * H_ + yt * YT_) * W_) * C_ + cg * CG_;

    #pragma unroll 2
    for (int yy = 0; yy < YT_; yy++) {
        #pragma unroll
        for (int r = 0; r < 2; r++) {
            const int cl = warp * 2 + r;
            float4 v = reinterpret_cast<const float4*>(
                           src + ((size_t)cl * H_ + yy) * W_)[lane];
            // local inclusive scan of 4
            v.y += v.x; v.z += v.y; v.w += v.z;
            // warp inclusive scan of lane totals
            float sum = v.w;
            #pragma unroll
            for (int off = 1; off < 32; off <<= 1) {
                float t = __shfl_up_sync(0xffffffffu, sum, off);
                if (lane >= off) sum += t;
            }
            const float pre = sum - v.w;       // exclusive prefix

            float4* a = r ? &acc1 : &acc0;
            a->x += v.x + pre;
            a->y += v.y + pre;
            a->z += v.z + pre;
            a->w += v.w + pre;

            s[cl][4 * lane + 0] = a->x;
            s[cl][4 * lane + 1] = a->y;
            s[cl][4 * lane + 2] = a->z;
            s[cl][4 * lane + 3] = a->w;
        }
        __syncthreads();

        float* dst = dstBase + (size_t)yy * (W_ * C_);
        #pragma unroll
        for (int i = tid; i < CG_ * W_; i += 256) {
            const int xx = i >> 4;
            const int cl = i & (CG_ - 1);
            dst[(size_t)xx * C_ + cl] = s[cl][xx];
        }
        __syncthreads();
    }

    // publish tile column sum (acc) to cs[b][yt][x][c]
    #pragma unroll
    for (int r = 0; r < 2; r++) {
        const int cl = warp * 2 + r;
        const float4 a = r ? acc1 : acc0;
        s[cl][4 * lane + 0] = a.x;
        s[cl][4 * lane + 1] = a.y;
        s[cl][4 * lane + 2] = a.z;
        s[cl][4 * lane + 3] = a.w;
    }
    __syncthreads();
    float* csrow = cs + ((size_t)(b * NT_ + yt) * W_) * C_ + cg * CG_;
    #pragma unroll
    for (int i = tid; i < CG_ * W_; i += 256) {
        const int xx = i >> 4;
        const int cl = i & (CG_ - 1);
        csrow[(size_t)xx * C_ + cl] = s[cl][xx];
    }
}

// ---------------------------------------------------------------------------
// K2': exclusive scan of cs over the 8 y-tiles -> off. Thread per (b,x,c).
// ---------------------------------------------------------------------------
__global__ __launch_bounds__(256) void k2_tilescan(const float* __restrict__ cs,
                                                   float* __restrict__ off) {
    const int g   = blockIdx.x * 256 + threadIdx.x;   // 0 .. B*W*C-1
    const int b   = g >> 15;
    const int rem = g & 32767;                        // x*C + c
    size_t base = (size_t)b * (NT_ * W_ * C_) + rem;
    const size_t str = (size_t)W_ * C_;

    float acc = 0.f;
    #pragma unroll
    for (int t = 0; t < NT_; t++) {
        const float v = cs[base];
        off[base] = acc;
        acc += v;
        base += str;
    }
}

// ---------------------------------------------------------------------------
// K3: gather. Grid = (B*Q, 4 cgroups of 64 ch). Corner value is
// tile-local SAT + tile offset. All loads coalesced across c.
// ---------------------------------------------------------------------------
__global__ __launch_bounds__(256) void k3_gather(const int* __restrict__ rois,
                                                 const float* __restrict__ S,
                                                 const float* __restrict__ off,
                                                 float* __restrict__ out) {
    const int bq = blockIdx.x;           // 0 .. B*Q-1
    const int cg = blockIdx.y;           // 0..3
    const int b  = bq / Q_;
    const int tid = threadIdx.x;

    __shared__ int   e_ys[OUT_], e_ye[OUT_], e_xs[OUT_], e_xe[OUT_];
    __shared__ float ia[BINS];
    __shared__ float stage[64][BINS + 2];

    const int* r = rois + bq * 5;        // [bidx, x1, y1, x2, y2]

    if (tid < OUT_) {
        int y1 = r[2], leny = r[4] - r[2];
        e_ys[tid] = y1 + (tid * leny) / OUT_;
        e_ye[tid] = y1 + ((tid + 1) * leny + (OUT_ - 1)) / OUT_;
    } else if (tid < 2 * OUT_) {
        int k = tid - OUT_;
        int x1 = r[1], lenx = r[3] - r[1];
        e_xs[k] = x1 + (k * lenx) / OUT_;
        e_xe[k] = x1 + ((k + 1) * lenx + (OUT_ - 1)) / OUT_;
    }
    __syncthreads();
    if (tid < BINS) {
        int oy = tid / OUT_, ox = tid % OUT_;
        ia[tid] = 1.0f / (float)((e_ye[oy] - e_ys[oy]) * (e_xe[ox] - e_xs[ox]));
    }
    __syncthreads();

    const int cl  = tid & 63;
    const int sub = tid >> 6;            // 0..3
    const int c   = cg * 64 + cl;
    const float* Sb = S   + (size_t)b * (H_ * W_ * C_);
    const float* Ob = off + (size_t)b * (NT_ * W_ * C_);

    #pragma unroll
    for (int bin = sub; bin < BINS; bin += 4) {
        const int oy = bin / OUT_, ox = bin % OUT_;
        const int Ys = e_ys[oy], Ye = e_ye[oy];
        const int Xs = e_xs[ox], Xe = e_xe[ox];

        // full-SAT corner = tile-local SAT + y-tile offset (0 at pad)
        auto corner = [&](int ey, int ex) -> float {
            if (ey == 0 || ex == 0) return 0.f;
            const size_t xi = (size_t)(ex - 1) * C_ + c;
            const float t = Sb[(size_t)(ey - 1) * (W_ * C_) + xi];
            const float o = Ob[(size_t)((ey - 1) >> 4) * (W_ * C_) + xi];
            return t + o;
        };

        const float see = corner(Ye, Xe);
        const float sse = corner(Ys, Xe);
        const float ses = corner(Ye, Xs);
        const float sss = corner(Ys, Xs);

        stage[cl][bin] = (see - sse - ses + sss) * ia[bin];
    }
    __syncthreads();

    float* ob = out + ((size_t)bq * C_ + cg * 64) * BINS;
    #pragma unroll 4
    for (int i = tid; i < 64 * BINS; i += 256) {
        ob[i] = stage[i / BINS][i % BINS];
    }
}

// ---------------------------------------------------------------------------
extern "C" void kernel_launch(void* const* d_in, const int* in_sizes, int n_in,
                              void* d_out, int out_size) {
    const float* x    = (const float*)d_in[0];
    const int*   rois = (const int*)d_in[1];
    float*       out  = (float*)d_out;

    float *sat, *cs, *off;
    cudaGetSymbolAddress((void**)&sat, g_sat);
    cudaGetSymbolAddress((void**)&cs,  g_cs);
    cudaGetSymbolAddress((void**)&off, g_off);

    k1_fused<<<B_ * NT_ * NCG_, 256>>>(x, sat, cs);

    k2_tilescan<<<(B_ * W_ * C_) / 256, 256>>>(cs, off);

    dim3 g3(B_ * Q_, 4);
    k3_gather<<<g3, 256>>>(rois, sat, off, out);
}